// round 9
// baseline (speedup 1.0000x reference)
#include <cuda_runtime.h>
#include <cuda_bf16.h>

#define T_STEPS  2048
#define NCHUNK   8
#define CH       (T_STEPS / NCHUNK)   // 256 steps per chunk
#define BATCH    4096
#define INSZ     8
#define HID      20
#define G4       80
#define GROUPS   3       // thread groups per CTA (lstm)
#define NGE      6       // batch elems per CTA (2 per thread group)
#define NTHREADS 64      // 2 warps; 60 active lanes
#define ROWW     24      // padded smem row (floats): h[0:20], pad

#define PRE_SLOTS   8    // (t,b) slots per iteration
#define PRE_THREADS 160  // 8 slots x 20 units
#define PRE_ITERS   16   // slot-iterations per CTA

// 2.68 GB scratch: pregate[t][b][j] = float4(xW+b for gates i,f,g,o)
__device__ float4 g_pre[(size_t)T_STEPS * BATCH * HID];
// chunk-boundary state
__device__ float g_h[BATCH * HID];
__device__ float g_c[BATCH * HID];

__device__ __forceinline__ float sigmoid_f(float v) {
    return __fdividef(1.0f, 1.0f + __expf(-v));
}
__device__ __forceinline__ float tanh_f(float v) {
    return __fdividef(2.0f, 1.0f + __expf(-2.0f * v)) - 1.0f;
}

// ---------------- Kernel 1: pregates = x @ W_ih + b_ih + b_hh for one chunk ----------------
// Small CTA (160 thr, ~10K regs) so it co-schedules beside resident lstm CTAs.
__global__ void __launch_bounds__(PRE_THREADS)
pre_kernel(const float* __restrict__ x,    // [T, B, 8]
           const float* __restrict__ Wih,  // [8, 80]
           const float* __restrict__ bih,  // [80]
           const float* __restrict__ bhh,  // [80]
           int t0)
{
    __shared__ __align__(16) float sx[2][PRE_SLOTS][INSZ];

    const int tid = threadIdx.x;
    const int s   = tid / HID;   // slot 0..7
    const int j   = tid % HID;   // unit 0..19

    // input-projection weights for unit j: 32 regs
    float w[INSZ][4];
#pragma unroll
    for (int k = 0; k < INSZ; k++)
#pragma unroll
        for (int q = 0; q < 4; q++)
            w[k][q] = __ldg(&Wih[k * G4 + q * HID + j]);
    const float bi0 = __ldg(&bih[0 * HID + j]) + __ldg(&bhh[0 * HID + j]);
    const float bi1 = __ldg(&bih[1 * HID + j]) + __ldg(&bhh[1 * HID + j]);
    const float bi2 = __ldg(&bih[2 * HID + j]) + __ldg(&bhh[2 * HID + j]);
    const float bi3 = __ldg(&bih[3 * HID + j]) + __ldg(&bhh[3 * HID + j]);

    // flattened slot index base for this CTA (slots are (t*BATCH + b), b fastest)
    const size_t base = (size_t)t0 * BATCH + (size_t)blockIdx.x * (PRE_SLOTS * PRE_ITERS);
    const float4* x4 = reinterpret_cast<const float4*>(x);

    // preload iter 0's x: 16 float4 = 8 slots x 32B, coalesced
    if (tid < PRE_SLOTS * 2)
        reinterpret_cast<float4*>(sx[0])[tid] = x4[base * 2 + tid];
    __syncthreads();

#pragma unroll 2
    for (int it = 0; it < PRE_ITERS; it++) {
        const int buf = it & 1;
        // prefetch next iteration's x into the other buffer
        if (it + 1 < PRE_ITERS && tid < PRE_SLOTS * 2)
            reinterpret_cast<float4*>(sx[buf ^ 1])[tid] =
                x4[(base + (size_t)(it + 1) * PRE_SLOTS) * 2 + tid];

        const float* xs = sx[buf][s];
        float a0 = bi0, a1 = bi1, a2 = bi2, a3 = bi3;
#pragma unroll
        for (int k = 0; k < INSZ; k++) {
            const float xv = xs[k];
            a0 = fmaf(xv, w[k][0], a0);
            a1 = fmaf(xv, w[k][1], a1);
            a2 = fmaf(xv, w[k][2], a2);
            a3 = fmaf(xv, w[k][3], a3);
        }
        const size_t n = base + (size_t)it * PRE_SLOTS + s;
        g_pre[n * HID + j] = make_float4(a0, a1, a2, a3);
        __syncthreads();
    }
}

// ---------------- Kernel 2: recurrence chunk over t in [t0, t0+CH) ----------------
__global__ void __launch_bounds__(NTHREADS, 5)
lstm_kernel(const float* __restrict__ Whh,  // [20, 80]
            const float* __restrict__ hx0,  // [1, 20]
            const float* __restrict__ cx0,  // [1, 20]
            float* __restrict__ out,        // [B, 20]
            int t0, int first)
{
    __shared__ __align__(16) float sv[2][NGE][ROWW];

    const int tid = threadIdx.x;
    const bool active = (tid < GROUPS * HID);   // 60 of 64
    const int tc  = active ? tid : 0;
    const int g   = tc / HID;             // 0..2
    const int j   = tc % HID;             // 0..19
    const int b0  = blockIdx.x * NGE + g;
    const int b1  = b0 + GROUPS;
    const bool ok0 = active && (b0 < BATCH);
    const bool ok1 = active && (b1 < BATCH);
    const int cb0 = (b0 < BATCH) ? b0 : 0;
    const int cb1 = (b1 < BATCH) ? b1 : 0;

    // ---- recurrent weights for unit j: 80 registers ----
    float w[HID][4];
#pragma unroll
    for (int k = 0; k < HID; k++)
#pragma unroll
        for (int q = 0; q < 4; q++)
            w[k][q] = __ldg(&Whh[k * G4 + q * HID + j]);

    float h0, c0, h1, c1;
    if (first) {
        h0 = hx0[j]; c0 = cx0[j];
        h1 = h0;     c1 = c0;
    } else {
        h0 = g_h[cb0 * HID + j]; c0 = g_c[cb0 * HID + j];
        h1 = g_h[cb1 * HID + j]; c1 = g_c[cb1 * HID + j];
    }

    // ---- pregate prefetch pipeline (2 steps deep) ----
    const size_t STRIDE = (size_t)BATCH * HID;
    const float4* p0 = g_pre + (size_t)t0 * STRIDE + (size_t)cb0 * HID + j;
    const float4* p1 = g_pre + (size_t)t0 * STRIDE + (size_t)cb1 * HID + j;
    float4 pc0 = p0[0],      pc1 = p1[0];        // local t = 0
    float4 pn0 = p0[STRIDE], pn1 = p1[STRIDE];   // local t = 1
    const float4* q0 = p0 + 2 * STRIDE;          // local t = 2 onward
    const float4* q1 = p1 + 2 * STRIDE;

    if (active) {
        sv[0][g][j]          = h0;
        sv[0][g + GROUPS][j] = h1;
    }
    __syncthreads();

    int cur = 0;
#pragma unroll 2
    for (int tt = 0; tt < CH; tt++) {
        const int nxt = cur ^ 1;

        // prefetch pregate for global step t0+tt+2
        float4 pf0 = make_float4(0.f, 0.f, 0.f, 0.f);
        float4 pf1 = pf0;
        if (t0 + tt + 2 < T_STEPS) { pf0 = *q0; pf1 = *q1; }
        q0 += STRIDE;
        q1 += STRIDE;

        float a00 = pc0.x, a01 = pc0.y, a02 = pc0.z, a03 = pc0.w;
        float a10 = pc1.x, a11 = pc1.y, a12 = pc1.z, a13 = pc1.w;

        const float4* r0 = reinterpret_cast<const float4*>(sv[cur][g]);
        const float4* r1 = reinterpret_cast<const float4*>(sv[cur][g + GROUPS]);
#pragma unroll
        for (int kc = 0; kc < HID / 4; kc++) {
            const float4 u = r0[kc];
            const float4 v = r1[kc];
            const int k = kc * 4;
            const float ua[4] = {u.x, u.y, u.z, u.w};
            const float va[4] = {v.x, v.y, v.z, v.w};
#pragma unroll
            for (int s = 0; s < 4; s++) {
                a00 = fmaf(ua[s], w[k + s][0], a00);
                a01 = fmaf(ua[s], w[k + s][1], a01);
                a02 = fmaf(ua[s], w[k + s][2], a02);
                a03 = fmaf(ua[s], w[k + s][3], a03);
                a10 = fmaf(va[s], w[k + s][0], a10);
                a11 = fmaf(va[s], w[k + s][1], a11);
                a12 = fmaf(va[s], w[k + s][2], a12);
                a13 = fmaf(va[s], w[k + s][3], a13);
            }
        }

        {
            float ii = sigmoid_f(a00);
            float ff = sigmoid_f(a01);
            float gg = tanh_f(a02);
            float oo = sigmoid_f(a03);
            c0 = ff * c0 + ii * gg;
            h0 = oo * tanh_f(c0);
        }
        {
            float ii = sigmoid_f(a10);
            float ff = sigmoid_f(a11);
            float gg = tanh_f(a12);
            float oo = sigmoid_f(a13);
            c1 = ff * c1 + ii * gg;
            h1 = oo * tanh_f(c1);
        }

        if (tt + 1 < CH) {
            if (active) {
                sv[nxt][g][j]          = h0;
                sv[nxt][g + GROUPS][j] = h1;
            }
            __syncthreads();
        }

        pc0 = pn0; pn0 = pf0;
        pc1 = pn1; pn1 = pf1;
        cur = nxt;
    }

    // persist chunk-boundary state; out overwritten each chunk (last chunk wins)
    if (ok0) {
        g_h[b0 * HID + j] = h0;
        g_c[b0 * HID + j] = c0;
        out[b0 * HID + j] = h0;
    }
    if (ok1) {
        g_h[b1 * HID + j] = h1;
        g_c[b1 * HID + j] = c1;
        out[b1 * HID + j] = h1;
    }
}

extern "C" void kernel_launch(void* const* d_in, const int* in_sizes, int n_in,
                              void* d_out, int out_size) {
    const float* x   = (const float*)d_in[0];
    const float* Wih = (const float*)d_in[1];
    const float* bih = (const float*)d_in[2];
    const float* Whh = (const float*)d_in[3];
    const float* bhh = (const float*)d_in[4];
    const float* hx0 = (const float*)d_in[5];
    const float* cx0 = (const float*)d_in[6];
    float* out = (float*)d_out;

    // one-time handle creation (first call is the uncaptured correctness run;
    // every call issues the identical launch/wait sequence).
    // Side stream gets the LOWEST priority so the work distributor prefers
    // lstm CTAs whenever both kernels have runnable CTAs.
    static cudaStream_t s1 = nullptr;
    static cudaEvent_t evF = nullptr;
    static cudaEvent_t ev[NCHUNK];
    if (s1 == nullptr) {
        int prLeast = 0, prGreatest = 0;
        cudaDeviceGetStreamPriorityRange(&prLeast, &prGreatest);
        cudaStreamCreateWithPriority(&s1, cudaStreamNonBlocking, prLeast);
        cudaEventCreateWithFlags(&evF, cudaEventDisableTiming);
        for (int k = 0; k < NCHUNK; k++)
            cudaEventCreateWithFlags(&ev[k], cudaEventDisableTiming);
    }

    // fork side stream from the main (captured) stream
    cudaEventRecord(evF, 0);
    cudaStreamWaitEvent(s1, evF, 0);

    const int pre_grid = (CH * BATCH) / (PRE_SLOTS * PRE_ITERS);  // 8192
    const int grid = (BATCH + NGE - 1) / NGE;                     // 683

    // INTERLEAVED submission: lstm chunk k is enqueued before pre chunk k+1,
    // so the dispatcher places lstm CTAs first and pre fills the holes.
    for (int k = 0; k < NCHUNK; k++) {
        pre_kernel<<<pre_grid, PRE_THREADS, 0, s1>>>(x, Wih, bih, bhh, k * CH);
        cudaEventRecord(ev[k], s1);
        cudaStreamWaitEvent(0, ev[k], 0);
        lstm_kernel<<<grid, NTHREADS>>>(Whh, hx0, cx0, out, k * CH, k == 0);
    }
}

// round 10
// speedup vs baseline: 1.1974x; 1.1974x over previous
#include <cuda_runtime.h>
#include <cuda_bf16.h>

#define T_STEPS  2048
#define BATCH    4096
#define INSZ     8
#define HID      20
#define G4       80
#define GROUPS   3       // thread groups per CTA
#define NGE      6       // batch elems per CTA (2 per thread group)
#define NTHREADS 64      // 2 warps; 60 active lanes
#define ROWW     24      // padded smem row (floats): h[0:20], pad

__device__ __forceinline__ float sigmoid_f(float v) {
    return __fdividef(1.0f, 1.0f + __expf(-v));
}
__device__ __forceinline__ float tanh_f(float v) {
    return __fdividef(2.0f, 1.0f + __expf(-2.0f * v)) - 1.0f;
}

__global__ void __launch_bounds__(NTHREADS)
lstm_kernel(const float* __restrict__ x,    // [T, B, 8]
            const float* __restrict__ Wih,  // [8, 80]
            const float* __restrict__ bih,  // [80]
            const float* __restrict__ Whh,  // [20, 80]
            const float* __restrict__ bhh,  // [80]
            const float* __restrict__ hx0,  // [1, 20]
            const float* __restrict__ cx0,  // [1, 20]
            float* __restrict__ out)        // [B, 20]
{
    __shared__ __align__(16) float sv[2][NGE][ROWW];

    const int tid = threadIdx.x;
    const bool active = (tid < GROUPS * HID);   // 60 of 64
    const int tc  = active ? tid : 0;
    const int g   = tc / HID;             // 0..2
    const int j   = tc % HID;             // 0..19
    const int b0  = blockIdx.x * NGE + g;
    const int b1  = b0 + GROUPS;
    const bool ok0 = active && (b0 < BATCH);
    const bool ok1 = active && (b1 < BATCH);
    const int cb0 = (b0 < BATCH) ? b0 : 0;
    const int cb1 = (b1 < BATCH) ? b1 : 0;

    // ---- recurrent weights (80 regs) + input weights (32 regs) for unit j ----
    float wh[HID][4];
#pragma unroll
    for (int k = 0; k < HID; k++)
#pragma unroll
        for (int q = 0; q < 4; q++)
            wh[k][q] = __ldg(&Whh[k * G4 + q * HID + j]);
    float wx[INSZ][4];
#pragma unroll
    for (int k = 0; k < INSZ; k++)
#pragma unroll
        for (int q = 0; q < 4; q++)
            wx[k][q] = __ldg(&Wih[k * G4 + q * HID + j]);

    float bias[4];
#pragma unroll
    for (int q = 0; q < 4; q++)
        bias[q] = __ldg(&bih[q * HID + j]) + __ldg(&bhh[q * HID + j]);

    float h0 = hx0[j], c0 = cx0[j];
    float h1 = h0,     c1 = c0;

    const float4* x4 = reinterpret_cast<const float4*>(x);
    // float4 index for (t, b, half): (t*BATCH + b)*2 + half

    // ---- prologue: xacc = bias + x_0 * W_ih for both elems ----
    float xacc0[4], xacc1[4];
    {
        const float4 a0 = x4[(0 * BATCH + cb0) * 2 + 0];
        const float4 a1 = x4[(0 * BATCH + cb0) * 2 + 1];
        const float4 b0v = x4[(0 * BATCH + cb1) * 2 + 0];
        const float4 b1v = x4[(0 * BATCH + cb1) * 2 + 1];
        const float xs0[8] = {a0.x, a0.y, a0.z, a0.w, a1.x, a1.y, a1.z, a1.w};
        const float xs1[8] = {b0v.x, b0v.y, b0v.z, b0v.w, b1v.x, b1v.y, b1v.z, b1v.w};
#pragma unroll
        for (int q = 0; q < 4; q++) { xacc0[q] = bias[q]; xacc1[q] = bias[q]; }
#pragma unroll
        for (int k = 0; k < INSZ; k++)
#pragma unroll
            for (int q = 0; q < 4; q++) {
                xacc0[q] = fmaf(xs0[k], wx[k][q], xacc0[q]);
                xacc1[q] = fmaf(xs1[k], wx[k][q], xacc1[q]);
            }
    }

    if (active) {
        sv[0][g][j]          = h0;
        sv[0][g + GROUPS][j] = h1;
    }
    __syncthreads();

    int cur = 0;
#pragma unroll 2
    for (int t = 0; t < T_STEPS; t++) {
        const int nxt = cur ^ 1;

        // ---- issue x loads for step t+1 early (latency hidden by FMA block) ----
        const int tn = (t + 1 < T_STEPS) ? (t + 1) : t;
        const float4 xa0 = x4[((size_t)tn * BATCH + cb0) * 2 + 0];
        const float4 xa1 = x4[((size_t)tn * BATCH + cb0) * 2 + 1];
        const float4 xb0 = x4[((size_t)tn * BATCH + cb1) * 2 + 0];
        const float4 xb1 = x4[((size_t)tn * BATCH + cb1) * 2 + 1];

        // ---- gate sums: start from precomputed x-part, add h·W_hh ----
        float a00 = xacc0[0], a01 = xacc0[1], a02 = xacc0[2], a03 = xacc0[3];
        float a10 = xacc1[0], a11 = xacc1[1], a12 = xacc1[2], a13 = xacc1[3];

        const float4* r0 = reinterpret_cast<const float4*>(sv[cur][g]);
        const float4* r1 = reinterpret_cast<const float4*>(sv[cur][g + GROUPS]);
#pragma unroll
        for (int kc = 0; kc < HID / 4; kc++) {
            const float4 u = r0[kc];
            const float4 v = r1[kc];
            const int k = kc * 4;
            const float ua[4] = {u.x, u.y, u.z, u.w};
            const float va[4] = {v.x, v.y, v.z, v.w};
#pragma unroll
            for (int s = 0; s < 4; s++) {
                a00 = fmaf(ua[s], wh[k + s][0], a00);
                a01 = fmaf(ua[s], wh[k + s][1], a01);
                a02 = fmaf(ua[s], wh[k + s][2], a02);
                a03 = fmaf(ua[s], wh[k + s][3], a03);
                a10 = fmaf(va[s], wh[k + s][0], a10);
                a11 = fmaf(va[s], wh[k + s][1], a11);
                a12 = fmaf(va[s], wh[k + s][2], a12);
                a13 = fmaf(va[s], wh[k + s][3], a13);
            }
        }

        // ---- activations (MUFU-heavy) ----
        const float ii0 = sigmoid_f(a00);
        const float ff0 = sigmoid_f(a01);
        const float gg0 = tanh_f(a02);
        const float oo0 = sigmoid_f(a03);
        const float ii1 = sigmoid_f(a10);
        const float ff1 = sigmoid_f(a11);
        const float gg1 = tanh_f(a12);
        const float oo1 = sigmoid_f(a13);

        // ---- next step's x-projection: independent work that fills the MUFU shadow ----
        {
            const float xs0[8] = {xa0.x, xa0.y, xa0.z, xa0.w, xa1.x, xa1.y, xa1.z, xa1.w};
            const float xs1[8] = {xb0.x, xb0.y, xb0.z, xb0.w, xb1.x, xb1.y, xb1.z, xb1.w};
#pragma unroll
            for (int q = 0; q < 4; q++) { xacc0[q] = bias[q]; xacc1[q] = bias[q]; }
#pragma unroll
            for (int k = 0; k < INSZ; k++)
#pragma unroll
                for (int q = 0; q < 4; q++) {
                    xacc0[q] = fmaf(xs0[k], wx[k][q], xacc0[q]);
                    xacc1[q] = fmaf(xs1[k], wx[k][q], xacc1[q]);
                }
        }

        // ---- state update ----
        c0 = ff0 * c0 + ii0 * gg0;
        c1 = ff1 * c1 + ii1 * gg1;
        h0 = oo0 * tanh_f(c0);
        h1 = oo1 * tanh_f(c1);

        if (t + 1 < T_STEPS) {
            if (active) {
                sv[nxt][g][j]          = h0;
                sv[nxt][g + GROUPS][j] = h1;
            }
            __syncthreads();
        }
        cur = nxt;
    }

    if (ok0) out[b0 * HID + j] = h0;
    if (ok1) out[b1 * HID + j] = h1;
}

extern "C" void kernel_launch(void* const* d_in, const int* in_sizes, int n_in,
                              void* d_out, int out_size) {
    const float* x   = (const float*)d_in[0];
    const float* Wih = (const float*)d_in[1];
    const float* bih = (const float*)d_in[2];
    const float* Whh = (const float*)d_in[3];
    const float* bhh = (const float*)d_in[4];
    const float* hx0 = (const float*)d_in[5];
    const float* cx0 = (const float*)d_in[6];
    float* out = (float*)d_out;

    const int grid = (BATCH + NGE - 1) / NGE;  // 683
    lstm_kernel<<<grid, NTHREADS>>>(x, Wih, bih, Whh, bhh, hx0, cx0, out);
}